// round 11
// baseline (speedup 1.0000x reference)
#include <cuda_runtime.h>
#include <cuda_bf16.h>
#include <cuda_fp16.h>
#include <math.h>
#include <stdint.h>

#define BATCH 16
#define NN 1024
#define DD 128
#define NBLK 15
#define CNT (BATCH*NN)
#define EPSV 1e-5f
#define LSCALE 256.0f
#define LINV (1.0f/256.0f)

// ---------------- scratch (no allocation allowed) ----------------
__device__ float g_buf0[BATCH*NN*DD];                 // 8 MB (x ping)
__device__ float g_buf1[BATCH*NN*DD];                 // 8 MB (x pong)
__device__ __half g_lhf[(size_t)BATCH*NN*NN];         // 32 MB  fp16(256*L)
__device__ __half g_whf[BATCH*DD*NN];                 // 4 MB  (h*Wk)^T fp16 [b][e][n]
__device__ __half g_wthf[NBLK*DD*DD];                 // W^T hi fp16 [k][e][d]
__device__ __half g_wtlf[NBLK*DD*DD];                 // W^T lo fp16
__device__ float g_stats[17*2*DD];                    // [slot][sum|sumsq][128]
__device__ float g_pooled[BATCH*DD];
__device__ float g_den[BATCH];

// ---------------- helpers ----------------
__device__ __forceinline__ uint32_t smem_u32(const void* p) {
    uint32_t a;
    asm("{ .reg .u64 t; cvta.to.shared.u64 t, %1; cvt.u32.u64 %0, t; }"
        : "=r"(a) : "l"(p));
    return a;
}
#define SWZ(o) ((o) ^ (((o) >> 3) & 0x70))

__device__ __forceinline__ void ldsm4(uint32_t* r, uint32_t a) {
    asm volatile("ldmatrix.sync.aligned.m8n8.x4.shared.b16 {%0,%1,%2,%3}, [%4];"
        : "=r"(r[0]), "=r"(r[1]), "=r"(r[2]), "=r"(r[3]) : "r"(a));
}
__device__ __forceinline__ void mma_f16(float* c, const uint32_t* a,
                                        uint32_t b0, uint32_t b1) {
    asm volatile("mma.sync.aligned.m16n8k16.row.col.f32.f16.f16.f32 "
        "{%0,%1,%2,%3}, {%4,%5,%6,%7}, {%8,%9}, {%0,%1,%2,%3};"
        : "+f"(c[0]), "+f"(c[1]), "+f"(c[2]), "+f"(c[3])
        : "r"(a[0]), "r"(a[1]), "r"(a[2]), "r"(a[3]), "r"(b0), "r"(b1));
}

// ---------------- small kernels ----------------
__global__ void zero_stats_kernel() {
    for (int i = threadIdx.x; i < 17*2*DD; i += blockDim.x) g_stats[i] = 0.f;
    for (int i = threadIdx.x; i < BATCH*DD; i += blockDim.x) g_pooled[i] = 0.f;
    if (threadIdx.x < BATCH) g_den[threadIdx.x] = 0.f;
}

__global__ void lconv_kernel(const float* __restrict__ L) {
    int g = blockIdx.x * 256 + threadIdx.x;
    float4 v = ((const float4*)L)[g];
    union { __half h[4]; uint2 u; } p;
    p.h[0] = __float2half(v.x * LSCALE);
    p.h[1] = __float2half(v.y * LSCALE);
    p.h[2] = __float2half(v.z * LSCALE);
    p.h[3] = __float2half(v.w * LSCALE);
    ((uint2*)g_lhf)[g] = p.u;
}

__global__ void wprep_all(const float* __restrict__ Wb) {
    int k = blockIdx.x;
    const float* W = Wb + k * DD * DD;
    __half* oh = g_wthf + k * DD * DD;
    __half* ol = g_wtlf + k * DD * DD;
    for (int i = threadIdx.x; i < DD * DD; i += blockDim.x) {
        int e = i >> 7, d = i & 127;
        float v = W[d * DD + e];
        __half hi = __float2half(v);
        oh[i] = hi;
        ol[i] = __float2half(v - __half2float(hi));
    }
}

__global__ void conv1_kernel(const float* __restrict__ inp,
                             const float* __restrict__ W1,
                             const float* __restrict__ b1) {
    int gid = blockIdx.x * blockDim.x + threadIdx.x;   // over B*N*32 float4s
    int row = gid >> 5, c4 = gid & 31;
    const float* x = inp + row * 3;
    float x0 = x[0], x1 = x[1], x2 = x[2];
    float4 w0 = *(const float4*)&W1[c4 * 4];
    float4 w1 = *(const float4*)&W1[128 + c4 * 4];
    float4 w2 = *(const float4*)&W1[256 + c4 * 4];
    float4 bv = *(const float4*)&b1[c4 * 4];
    float4 o;
    o.x = fmaf(x0, w0.x, fmaf(x1, w1.x, fmaf(x2, w2.x, bv.x)));
    o.y = fmaf(x0, w0.y, fmaf(x1, w1.y, fmaf(x2, w2.y, bv.y)));
    o.z = fmaf(x0, w0.z, fmaf(x1, w1.z, fmaf(x2, w2.z, bv.z)));
    o.w = fmaf(x0, w0.w, fmaf(x1, w1.w, fmaf(x2, w2.w, bv.w)));
    ((float4*)g_buf0)[gid] = o;
    ((float4*)g_buf1)[gid] = make_float4(0.f, 0.f, 0.f, 0.f);
}

__global__ void stats_kernel(const float* __restrict__ x, int slot) {
    int c = threadIdx.x & 127, half = threadIdx.x >> 7;
    int row0 = blockIdx.x * 64;
    float s = 0.f, q = 0.f;
    for (int i = half; i < 64; i += 2) {
        float v = x[(row0 + i) * DD + c];
        s += v; q += v * v;
    }
    __shared__ float ss[256], qq[256];
    ss[threadIdx.x] = s; qq[threadIdx.x] = q;
    __syncthreads();
    if (half == 0) {
        s += ss[c + 128]; q += qq[c + 128];
        atomicAdd(&g_stats[slot * 256 + c], s);
        atomicAdd(&g_stats[slot * 256 + 128 + c], q);
    }
}

// ---------------- bnelu + (h*Wk)^T via fp16 tensor cores (3-pass) ----------------
// SMEM: W_hi 2x16K at 0, W_lo 2x16K at 32K, h_hi 2x16K at 64K, h_lo 2x16K at 96K
#define BM_SMEM 131072
__global__ void __launch_bounds__(256)
bnelu_mma(const float* __restrict__ x, int blk,
          const float* __restrict__ gam, const float* __restrict__ bet, int slot) {
    extern __shared__ __align__(1024) char sm[];
    const uint32_t smb = smem_u32(sm);
    __shared__ float sc[128], tsh[128];
    const int tid = threadIdx.x, w = tid >> 5, l = tid & 31;
    const int b = blockIdx.y, nt = blockIdx.x;

    if (tid < 128) {
        float s = g_stats[slot * 256 + tid], q = g_stats[slot * 256 + 128 + tid];
        float mean = s * (1.f / CNT), var = q * (1.f / CNT) - mean * mean;
        float k = gam[tid] * rsqrtf(var + EPSV);
        sc[tid] = k; tsh[tid] = bet[tid] - mean * k;
    }

    const __half* wth = g_wthf + blk * DD * DD;
    const __half* wtl = g_wtlf + blk * DD * DD;
    #pragma unroll
    for (int i = 0; i < 8; i++) {
        int c = i * 256 + tid;                    // 16B chunk over 2048
        int e = c >> 4, ch = c & 15;
        uint32_t off = (uint32_t)(ch >> 3) * 16384 + SWZ(e * 128 + (ch & 7) * 16);
        *(float4*)(sm + off) = *(const float4*)(wth + e * 128 + ch * 8);
        *(float4*)(sm + 32768 + off) = *(const float4*)(wtl + e * 128 + ch * 8);
    }
    __syncthreads();

    const float* xb = x + ((size_t)b << 17) + (size_t)nt * 128 * DD;
    #pragma unroll 8
    for (int i = 0; i < 64; i++) {
        int idx = i * 256 + tid;
        int n = idx >> 7, d = idx & 127;
        float v = fmaf(sc[d], xb[idx], tsh[d]);
        v = (v > 0.f) ? v : expm1f(v);
        __half hi = __float2half(v);
        __half lo = __float2half(v - __half2float(hi));
        uint32_t o = (uint32_t)(d >> 6) * 16384 + SWZ(n * 128 + (d & 63) * 2);
        *(__half*)(sm + 65536 + o) = hi;
        *(__half*)(sm + 98304 + o) = lo;
    }
    __syncthreads();

    float acc[2][8][4] = {};
    const int mwo = (w & 3) * 32, nwo = (w >> 2) * 64;
    const int aRow = l & 15, selB = l >> 4;
    const int bRow = (l & 7) + (((l >> 3) & 1) << 3);

    #pragma unroll
    for (int ks = 0; ks < 2; ks++) {
        uint32_t Ah = smb + ks * 16384;
        uint32_t Al = smb + 32768 + ks * 16384;
        uint32_t Bh = smb + 65536 + ks * 16384;
        uint32_t Bl = smb + 98304 + ks * 16384;
        #pragma unroll
        for (int t = 0; t < 4; t++) {
            const int kb = t * 32 + selB * 16;
            uint32_t ah[2][4], al[2][4], bh[4][4], bl[4][4];
            #pragma unroll
            for (int m = 0; m < 2; m++) {
                uint32_t ro = (mwo + m * 16 + aRow) * 128 + kb;
                ldsm4(ah[m], Ah + SWZ(ro));
                ldsm4(al[m], Al + SWZ(ro));
            }
            #pragma unroll
            for (int ng = 0; ng < 4; ng++) {
                uint32_t ro = (nwo + ng * 16 + bRow) * 128 + kb;
                ldsm4(bh[ng], Bh + SWZ(ro));
                ldsm4(bl[ng], Bl + SWZ(ro));
            }
            // pass 1: W_hi * h_hi
            #pragma unroll
            for (int m = 0; m < 2; m++)
                #pragma unroll
                for (int ng = 0; ng < 4; ng++) {
                    mma_f16(acc[m][2*ng],   ah[m], bh[ng][0], bh[ng][2]);
                    mma_f16(acc[m][2*ng+1], ah[m], bh[ng][1], bh[ng][3]);
                }
            // pass 2: W_lo * h_hi
            #pragma unroll
            for (int m = 0; m < 2; m++)
                #pragma unroll
                for (int ng = 0; ng < 4; ng++) {
                    mma_f16(acc[m][2*ng],   al[m], bh[ng][0], bh[ng][2]);
                    mma_f16(acc[m][2*ng+1], al[m], bh[ng][1], bh[ng][3]);
                }
            // pass 3: W_hi * h_lo
            #pragma unroll
            for (int m = 0; m < 2; m++)
                #pragma unroll
                for (int ng = 0; ng < 4; ng++) {
                    mma_f16(acc[m][2*ng],   ah[m], bl[ng][0], bl[ng][2]);
                    mma_f16(acc[m][2*ng+1], ah[m], bl[ng][1], bl[ng][3]);
                }
        }
    }
    __syncthreads();

    float* red = (float*)sm;                   // 128 x 132  (rows = e, cols = n)
    const int r4 = l >> 2, c2 = (l & 3) * 2;
    #pragma unroll
    for (int m = 0; m < 2; m++)
        #pragma unroll
        for (int ntile = 0; ntile < 8; ntile++) {
            int row = mwo + m * 16 + r4, col = nwo + ntile * 8 + c2;
            *(float2*)&red[row * 132 + col] = make_float2(acc[m][ntile][0], acc[m][ntile][1]);
            *(float2*)&red[(row + 8) * 132 + col] = make_float2(acc[m][ntile][2], acc[m][ntile][3]);
        }
    __syncthreads();

    const size_t obase = (size_t)b * (DD * NN) + (size_t)nt * 128;
    #pragma unroll 8
    for (int i = 0; i < 64; i++) {
        int idx = i * 256 + tid;
        int e = idx >> 7, n = idx & 127;
        g_whf[obase + (size_t)e * NN + n] = __float2half(red[e * 132 + n]);
    }
}

// ---------------- fp16 warp-MMA big GEMM (1-pass, 3-stage, 1 barrier/kc) ----------------
// grid (8, 16), 256 threads (8 warps, 32x64 warp tiles).
// Stages: 3 x (A 16K + B 16K) = 96 KB >= epilogue staging 128x132 f32 = 66 KB.
#define MM_SMEM 98304
__global__ void __launch_bounds__(256)
mma_gemm(float* __restrict__ xb, const float* __restrict__ bk, int slot) {
    extern __shared__ __align__(1024) char sm[];
    const uint32_t smb = smem_u32(sm);
    const int tid = threadIdx.x, w = tid >> 5, l = tid & 31;
    const int b = blockIdx.y, mt8 = blockIdx.x;

    const size_t aoff = (size_t)b * NN * NN + (size_t)mt8 * 128 * NN;
    const size_t boff = (size_t)b * (DD * NN);
    const __half* srcp[2] = { g_lhf + aoff, g_whf + boff };

    auto load_stage = [&](int kc, int st) {
        uint32_t dst0 = smb + st * 32768;
        #pragma unroll
        for (int i = 0; i < 8; i++) {
            int c = i * 256 + tid;                 // 0..2047
            int mat = c >> 10, r = (c >> 3) & 127, q = c & 7;
            const __half* s = srcp[mat] + (size_t)r * NN + kc * 64 + q * 8;
            uint32_t d = dst0 + mat * 16384 + SWZ(r * 128 + q * 16);
            asm volatile("cp.async.cg.shared.global [%0], [%1], 16;" :: "r"(d), "l"(s));
        }
        asm volatile("cp.async.commit_group;" ::: "memory");
    };

    float acc[2][8][4] = {};
    const int mwo = (w & 3) * 32, nwo = (w >> 2) * 64;
    const int aRow = l & 15, selB = l >> 4;
    const int bRow = (l & 7) + (((l >> 3) & 1) << 3);

    load_stage(0, 0);
    load_stage(1, 1);
    // mainloop: wait(stage kc) -> barrier (visibility + stage (kc-1)%3 free) ->
    //           issue load(kc+2) into (kc+2)%3 == (kc-1)%3 -> compute(kc)
    for (int kc = 0; kc < 16; kc++) {
        if (kc < 15) {
            asm volatile("cp.async.wait_group 1;" ::: "memory");
        } else {
            asm volatile("cp.async.wait_group 0;" ::: "memory");
        }
        __syncthreads();
        if (kc + 2 < 16) load_stage(kc + 2, (kc + 2) % 3);
        uint32_t sb = smb + (kc % 3) * 32768;
        #pragma unroll
        for (int t = 0; t < 4; t++) {
            const int kb = t * 32 + selB * 16;
            uint32_t ah[2][4], bh[4][4];
            #pragma unroll
            for (int m = 0; m < 2; m++) {
                uint32_t ro = (mwo + m * 16 + aRow) * 128 + kb;
                ldsm4(ah[m], sb + SWZ(ro));
            }
            #pragma unroll
            for (int ng = 0; ng < 4; ng++) {
                uint32_t ro = (nwo + ng * 16 + bRow) * 128 + kb;
                ldsm4(bh[ng], sb + 16384 + SWZ(ro));
            }
            #pragma unroll
            for (int m = 0; m < 2; m++)
                #pragma unroll
                for (int ng = 0; ng < 4; ng++) {
                    mma_f16(acc[m][2*ng],   ah[m], bh[ng][0], bh[ng][2]);
                    mma_f16(acc[m][2*ng+1], ah[m], bh[ng][1], bh[ng][3]);
                }
        }
    }
    __syncthreads();   // all reads done before epilogue staging overwrites

    // ---- epilogue: accums -> SMEM (scaled), residual + bias + fused BN stats ----
    float* red = (float*)sm;                       // 128 x 132 f32 = 67584 B < 98304
    const int r4 = l >> 2, c2 = (l & 3) * 2;
    #pragma unroll
    for (int m = 0; m < 2; m++)
        #pragma unroll
        for (int nt = 0; nt < 8; nt++) {
            int row = mwo + m * 16 + r4, col = nwo + nt * 8 + c2;
            *(float2*)&red[row * 132 + col] =
                make_float2(acc[m][nt][0] * LINV, acc[m][nt][1] * LINV);
            *(float2*)&red[(row + 8) * 132 + col] =
                make_float2(acc[m][nt][2] * LINV, acc[m][nt][3] * LINV);
        }
    __syncthreads();

    float* xbb = xb + ((size_t)b << 17) + (size_t)mt8 * 128 * DD;
    const int cc = tid & 127;
    const float bkv = bk[cc];
    float s = 0.f, q = 0.f;
    #pragma unroll 8
    for (int i = 0; i < 64; i++) {
        int idx = i * 256 + tid;
        int row = idx >> 7;
        float o = xbb[idx] + red[row * 132 + cc] + bkv;
        xbb[idx] = o;
        s += o; q += o * o;
    }
    __syncthreads();
    float* ss = red;                               // reuse staging
    float* qq = red + 256;
    ss[tid] = s; qq[tid] = q;
    __syncthreads();
    if (tid < 128) {
        s = ss[tid] + ss[tid + 128];
        q = qq[tid] + qq[tid + 128];
        atomicAdd(&g_stats[slot * 256 + tid], s);
        atomicAdd(&g_stats[slot * 256 + 128 + tid], q);
    }
}

// ---------------- pool (partial, atomics) + output ----------------
__global__ void pool_kernel(const float* __restrict__ xa, const float* __restrict__ xb,
                            const float* __restrict__ mask,
                            const float* __restrict__ g1, const float* __restrict__ be1,
                            const float* __restrict__ g2, const float* __restrict__ be2,
                            int slot1, int slot2) {
    int b = blockIdx.x, seg = blockIdx.y, t = threadIdx.x;
    int c = t & 127, half = t >> 7;
    __shared__ float s1[128], t1s[128], s2[128], t2s[128];
    if (t < 128) {
        float s = g_stats[slot1 * 256 + t], q = g_stats[slot1 * 256 + 128 + t];
        float mean = s * (1.f / CNT), var = q * (1.f / CNT) - mean * mean;
        float sc = g1[t] * rsqrtf(var + EPSV);
        s1[t] = sc; t1s[t] = be1[t] - mean * sc;
        s = g_stats[slot2 * 256 + t]; q = g_stats[slot2 * 256 + 128 + t];
        mean = s * (1.f / CNT); var = q * (1.f / CNT) - mean * mean;
        sc = g2[t] * rsqrtf(var + EPSV);
        s2[t] = sc; t2s[t] = be2[t] - mean * sc;
    }
    __syncthreads();
    float acc = 0.f, msum = 0.f;
    int r0 = seg * 128;
    for (int i = half; i < 128; i += 2) {
        int r = r0 + i;
        float m = mask[b * NN + r];
        float v = fmaf(s1[c], xa[(b * NN + r) * DD + c], t1s[c]) +
                  fmaf(s2[c], xb[(b * NN + r) * DD + c], t2s[c]);
        v = (v > 0.f) ? v : expm1f(v);
        acc += m * v;
        if (c == 0) msum += m;
    }
    __shared__ float red[256];
    red[t] = acc;
    __syncthreads();
    if (half == 0) atomicAdd(&g_pooled[b * DD + c], red[c] + red[c + 128]);
    __syncthreads();
    red[t] = (c == 0) ? msum : 0.f;
    __syncthreads();
    if (t == 0) atomicAdd(&g_den[b], red[0] + red[128]);
}

__global__ void out_kernel(const float* __restrict__ W2, const float* __restrict__ b2,
                           float* __restrict__ out) {
    int b = blockIdx.x, d = threadIdx.x;
    __shared__ float p[128];
    p[d] = g_pooled[b * DD + d];
    __syncthreads();
    float inv = 1.f / g_den[b];
    float accv = 0.f;
    #pragma unroll 4
    for (int c = 0; c < 128; c++) accv = fmaf(p[c], W2[c * 128 + d], accv);
    out[b * 128 + d] = accv * inv + b2[d];
}

// ---------------- host ----------------
extern "C" void kernel_launch(void* const* d_in, const int* in_sizes, int n_in,
                              void* d_out, int out_size) {
    const float* inputs = (const float*)d_in[0];
    const float* Lmat   = (const float*)d_in[1];
    const float* mask   = (const float*)d_in[2];
    const float* W1     = (const float*)d_in[3];
    const float* b1     = (const float*)d_in[4];
    const float* Wb     = (const float*)d_in[5];
    const float* bb     = (const float*)d_in[6];
    const float* gb     = (const float*)d_in[7];
    const float* beb    = (const float*)d_in[8];
    const float* g1     = (const float*)d_in[9];
    const float* be1    = (const float*)d_in[10];
    const float* g2     = (const float*)d_in[11];
    const float* be2    = (const float*)d_in[12];
    const float* W2     = (const float*)d_in[13];
    const float* b2     = (const float*)d_in[14];
    float* out = (float*)d_out;

    float *buf0, *buf1;
    cudaGetSymbolAddress((void**)&buf0, g_buf0);
    cudaGetSymbolAddress((void**)&buf1, g_buf1);

    cudaFuncSetAttribute(mma_gemm, cudaFuncAttributeMaxDynamicSharedMemorySize, MM_SMEM);
    cudaFuncSetAttribute(bnelu_mma, cudaFuncAttributeMaxDynamicSharedMemorySize, BM_SMEM);

    zero_stats_kernel<<<1, 256>>>();
    lconv_kernel<<<(BATCH * NN * NN) / 4 / 256, 256>>>(Lmat);
    wprep_all<<<NBLK, 256>>>(Wb);
    conv1_kernel<<<(BATCH * NN * 32) / 256, 256>>>(inputs, W1, b1);
    stats_kernel<<<256, 256>>>(buf0, 0);

    float* pa = buf0;   // x1
    float* pb = buf1;   // x2
    for (int k = 0; k < NBLK; k++) {
        dim3 grid(8, 16);
        bnelu_mma<<<grid, 256, BM_SMEM>>>(pa, k, gb + k * DD, beb + k * DD, k);
        mma_gemm<<<grid, 256, MM_SMEM>>>(pb, bb + k * DD, k + 1);
        float* tmp = pa; pa = pb; pb = tmp;
    }
    // pa = x1_final (stats slot 15), pb = x2_final (stats slot 14)
    dim3 pgrid(BATCH, 8);
    pool_kernel<<<pgrid, 256>>>(pa, pb, mask, g1, be1, g2, be2, NBLK, NBLK - 1);
    out_kernel<<<BATCH, 128>>>(W2, b2, out);
}

// round 12
// speedup vs baseline: 1.0969x; 1.0969x over previous
#include <cuda_runtime.h>
#include <cuda_bf16.h>
#include <cuda_fp16.h>
#include <math.h>
#include <stdint.h>

#define BATCH 16
#define NN 1024
#define DD 128
#define NBLK 15
#define CNT (BATCH*NN)
#define EPSV 1e-5f
#define LSCALE 256.0f
#define LINV (1.0f/256.0f)

// ---------------- scratch (no allocation allowed) ----------------
__device__ float g_buf0[BATCH*NN*DD];                 // 8 MB (x ping)
__device__ float g_buf1[BATCH*NN*DD];                 // 8 MB (x pong)
__device__ __half g_lhf[(size_t)BATCH*NN*NN];         // 32 MB  fp16(256*L)
__device__ __half g_whf[BATCH*DD*NN];                 // 4 MB  (h*Wk)^T fp16 [b][e][n]
__device__ __half g_wthf[NBLK*DD*DD];                 // W^T hi fp16 [k][e][d]
__device__ __half g_wtlf[NBLK*DD*DD];                 // W^T lo fp16
__device__ float g_stats[17*2*DD];                    // [slot][sum|sumsq][128]
__device__ float g_pooled[BATCH*DD];
__device__ float g_den[BATCH];

// ---------------- helpers ----------------
__device__ __forceinline__ uint32_t smem_u32(const void* p) {
    uint32_t a;
    asm("{ .reg .u64 t; cvta.to.shared.u64 t, %1; cvt.u32.u64 %0, t; }"
        : "=r"(a) : "l"(p));
    return a;
}
#define SWZ(o) ((o) ^ (((o) >> 3) & 0x70))

__device__ __forceinline__ void ldsm4(uint32_t* r, uint32_t a) {
    asm volatile("ldmatrix.sync.aligned.m8n8.x4.shared.b16 {%0,%1,%2,%3}, [%4];"
        : "=r"(r[0]), "=r"(r[1]), "=r"(r[2]), "=r"(r[3]) : "r"(a));
}
__device__ __forceinline__ void mma_f16(float* c, const uint32_t* a,
                                        uint32_t b0, uint32_t b1) {
    asm volatile("mma.sync.aligned.m16n8k16.row.col.f32.f16.f16.f32 "
        "{%0,%1,%2,%3}, {%4,%5,%6,%7}, {%8,%9}, {%0,%1,%2,%3};"
        : "+f"(c[0]), "+f"(c[1]), "+f"(c[2]), "+f"(c[3])
        : "r"(a[0]), "r"(a[1]), "r"(a[2]), "r"(a[3]), "r"(b0), "r"(b1));
}

// ---------------- small kernels ----------------
// lconv also zeroes the stats/pool scratch (block 0) — saves a launch.
__global__ void lconv_kernel(const float* __restrict__ L) {
    if (blockIdx.x == 0) {
        for (int i = threadIdx.x; i < 17*2*DD; i += 256) g_stats[i] = 0.f;
        for (int i = threadIdx.x; i < BATCH*DD; i += 256) g_pooled[i] = 0.f;
        if (threadIdx.x < BATCH) g_den[threadIdx.x] = 0.f;
    }
    int g = blockIdx.x * 256 + threadIdx.x;
    float4 v = ((const float4*)L)[g];
    union { __half h[4]; uint2 u; } p;
    p.h[0] = __float2half(v.x * LSCALE);
    p.h[1] = __float2half(v.y * LSCALE);
    p.h[2] = __float2half(v.z * LSCALE);
    p.h[3] = __float2half(v.w * LSCALE);
    ((uint2*)g_lhf)[g] = p.u;
}

__global__ void wprep_all(const float* __restrict__ Wb) {
    int k = blockIdx.x;
    const float* W = Wb + k * DD * DD;
    __half* oh = g_wthf + k * DD * DD;
    __half* ol = g_wtlf + k * DD * DD;
    for (int i = threadIdx.x; i < DD * DD; i += blockDim.x) {
        int e = i >> 7, d = i & 127;
        float v = W[d * DD + e];
        __half hi = __float2half(v);
        oh[i] = hi;
        ol[i] = __float2half(v - __half2float(hi));
    }
}

__global__ void conv1_kernel(const float* __restrict__ inp,
                             const float* __restrict__ W1,
                             const float* __restrict__ b1) {
    int gid = blockIdx.x * blockDim.x + threadIdx.x;   // over B*N*32 float4s
    int row = gid >> 5, c4 = gid & 31;
    const float* x = inp + row * 3;
    float x0 = x[0], x1 = x[1], x2 = x[2];
    float4 w0 = *(const float4*)&W1[c4 * 4];
    float4 w1 = *(const float4*)&W1[128 + c4 * 4];
    float4 w2 = *(const float4*)&W1[256 + c4 * 4];
    float4 bv = *(const float4*)&b1[c4 * 4];
    float4 o;
    o.x = fmaf(x0, w0.x, fmaf(x1, w1.x, fmaf(x2, w2.x, bv.x)));
    o.y = fmaf(x0, w0.y, fmaf(x1, w1.y, fmaf(x2, w2.y, bv.y)));
    o.z = fmaf(x0, w0.z, fmaf(x1, w1.z, fmaf(x2, w2.z, bv.z)));
    o.w = fmaf(x0, w0.w, fmaf(x1, w1.w, fmaf(x2, w2.w, bv.w)));
    ((float4*)g_buf0)[gid] = o;
    ((float4*)g_buf1)[gid] = make_float4(0.f, 0.f, 0.f, 0.f);
}

__global__ void stats_kernel(const float* __restrict__ x, int slot) {
    int c = threadIdx.x & 127, half = threadIdx.x >> 7;
    int row0 = blockIdx.x * 64;
    float s = 0.f, q = 0.f;
    for (int i = half; i < 64; i += 2) {
        float v = x[(row0 + i) * DD + c];
        s += v; q += v * v;
    }
    __shared__ float ss[256], qq[256];
    ss[threadIdx.x] = s; qq[threadIdx.x] = q;
    __syncthreads();
    if (half == 0) {
        s += ss[c + 128]; q += qq[c + 128];
        atomicAdd(&g_stats[slot * 256 + c], s);
        atomicAdd(&g_stats[slot * 256 + 128 + c], q);
    }
}

// ---------------- bnelu + (h*Wk)^T via fp16 tensor cores (2-pass, W hi/lo) ----------------
// SMEM: W_hi 2x16K at 0, W_lo 2x16K at 32K, h 2x16K at 64K  => 96 KB
#define BM_SMEM 98304
__global__ void __launch_bounds__(256)
bnelu_mma(const float* __restrict__ x, int blk,
          const float* __restrict__ gam, const float* __restrict__ bet, int slot) {
    extern __shared__ __align__(1024) char sm[];
    const uint32_t smb = smem_u32(sm);
    __shared__ float sc[128], tsh[128];
    const int tid = threadIdx.x, w = tid >> 5, l = tid & 31;
    const int b = blockIdx.y, nt = blockIdx.x;

    if (tid < 128) {
        float s = g_stats[slot * 256 + tid], q = g_stats[slot * 256 + 128 + tid];
        float mean = s * (1.f / CNT), var = q * (1.f / CNT) - mean * mean;
        float k = gam[tid] * rsqrtf(var + EPSV);
        sc[tid] = k; tsh[tid] = bet[tid] - mean * k;
    }

    const __half* wth = g_wthf + blk * DD * DD;
    const __half* wtl = g_wtlf + blk * DD * DD;
    #pragma unroll
    for (int i = 0; i < 8; i++) {
        int c = i * 256 + tid;                    // 16B chunk over 2048
        int e = c >> 4, ch = c & 15;
        uint32_t off = (uint32_t)(ch >> 3) * 16384 + SWZ(e * 128 + (ch & 7) * 16);
        *(float4*)(sm + off) = *(const float4*)(wth + e * 128 + ch * 8);
        *(float4*)(sm + 32768 + off) = *(const float4*)(wtl + e * 128 + ch * 8);
    }
    __syncthreads();

    const float* xb = x + ((size_t)b << 17) + (size_t)nt * 128 * DD;
    #pragma unroll 8
    for (int i = 0; i < 64; i++) {
        int idx = i * 256 + tid;
        int n = idx >> 7, d = idx & 127;
        float v = fmaf(sc[d], xb[idx], tsh[d]);
        v = (v > 0.f) ? v : expm1f(v);
        uint32_t o = (uint32_t)(d >> 6) * 16384 + SWZ(n * 128 + (d & 63) * 2);
        *(__half*)(sm + 65536 + o) = __float2half(v);
    }
    __syncthreads();

    float acc[2][8][4] = {};
    const int mwo = (w & 3) * 32, nwo = (w >> 2) * 64;
    const int aRow = l & 15, selB = l >> 4;
    const int bRow = (l & 7) + (((l >> 3) & 1) << 3);

    #pragma unroll
    for (int ks = 0; ks < 2; ks++) {
        uint32_t Ah = smb + ks * 16384;
        uint32_t Al = smb + 32768 + ks * 16384;
        uint32_t Bh = smb + 65536 + ks * 16384;
        #pragma unroll
        for (int t = 0; t < 4; t++) {
            const int kb = t * 32 + selB * 16;
            uint32_t ah[2][4], al[2][4], bh[4][4];
            #pragma unroll
            for (int m = 0; m < 2; m++) {
                uint32_t ro = (mwo + m * 16 + aRow) * 128 + kb;
                ldsm4(ah[m], Ah + SWZ(ro));
                ldsm4(al[m], Al + SWZ(ro));
            }
            #pragma unroll
            for (int ng = 0; ng < 4; ng++) {
                uint32_t ro = (nwo + ng * 16 + bRow) * 128 + kb;
                ldsm4(bh[ng], Bh + SWZ(ro));
            }
            // pass 1: W_hi * h
            #pragma unroll
            for (int m = 0; m < 2; m++)
                #pragma unroll
                for (int ng = 0; ng < 4; ng++) {
                    mma_f16(acc[m][2*ng],   ah[m], bh[ng][0], bh[ng][2]);
                    mma_f16(acc[m][2*ng+1], ah[m], bh[ng][1], bh[ng][3]);
                }
            // pass 2: W_lo * h
            #pragma unroll
            for (int m = 0; m < 2; m++)
                #pragma unroll
                for (int ng = 0; ng < 4; ng++) {
                    mma_f16(acc[m][2*ng],   al[m], bh[ng][0], bh[ng][2]);
                    mma_f16(acc[m][2*ng+1], al[m], bh[ng][1], bh[ng][3]);
                }
        }
    }
    __syncthreads();

    float* red = (float*)sm;                   // 128 x 132  (rows = e, cols = n)
    const int r4 = l >> 2, c2 = (l & 3) * 2;
    #pragma unroll
    for (int m = 0; m < 2; m++)
        #pragma unroll
        for (int ntile = 0; ntile < 8; ntile++) {
            int row = mwo + m * 16 + r4, col = nwo + ntile * 8 + c2;
            *(float2*)&red[row * 132 + col] = make_float2(acc[m][ntile][0], acc[m][ntile][1]);
            *(float2*)&red[(row + 8) * 132 + col] = make_float2(acc[m][ntile][2], acc[m][ntile][3]);
        }
    __syncthreads();

    const size_t obase = (size_t)b * (DD * NN) + (size_t)nt * 128;
    #pragma unroll 8
    for (int i = 0; i < 64; i++) {
        int idx = i * 256 + tid;
        int e = idx >> 7, n = idx & 127;
        g_whf[obase + (size_t)e * NN + n] = __float2half(red[e * 132 + n]);
    }
}

// ---------------- fp16 warp-MMA big GEMM (1-pass, BK=128, 3-stage) ----------------
// grid (8, 16), 256 threads (8 warps, 32x64 warp tiles).
// Stage = A[128x128] 32K (two 16K k-blocks) + B same = 64 KB; 3 stages = 192 KB.
// 8 k-chunks of 128 -> half the barriers of BK=64.
#define MM_SMEM 196608
__global__ void __launch_bounds__(256)
mma_gemm(float* __restrict__ xb, const float* __restrict__ bk, int slot) {
    extern __shared__ __align__(1024) char sm[];
    const uint32_t smb = smem_u32(sm);
    const int tid = threadIdx.x, w = tid >> 5, l = tid & 31;
    const int b = blockIdx.y, mt8 = blockIdx.x;

    const size_t aoff = (size_t)b * NN * NN + (size_t)mt8 * 128 * NN;
    const size_t boff = (size_t)b * (DD * NN);
    const __half* srcp[2] = { g_lhf + aoff, g_whf + boff };

    // stage layout: mat(A/B) * 32768 + kblk * 16384 + SWZ(row*128 + q*16)
    auto load_stage = [&](int kc, int st) {
        uint32_t dst0 = smb + st * 65536;
        #pragma unroll
        for (int i = 0; i < 16; i++) {
            int c = i * 256 + tid;                 // 0..4095 16B chunks
            int mat = c >> 11, rem = c & 2047;
            int r = rem >> 4, ch = rem & 15;
            int kblk = ch >> 3, q = ch & 7;
            const __half* s = srcp[mat] + (size_t)r * NN + kc * 128 + kblk * 64 + q * 8;
            uint32_t d = dst0 + mat * 32768 + kblk * 16384 + SWZ(r * 128 + q * 16);
            asm volatile("cp.async.cg.shared.global [%0], [%1], 16;" :: "r"(d), "l"(s));
        }
        asm volatile("cp.async.commit_group;" ::: "memory");
    };

    float acc[2][8][4] = {};
    const int mwo = (w & 3) * 32, nwo = (w >> 2) * 64;
    const int aRow = l & 15, selB = l >> 4;
    const int bRow = (l & 7) + (((l >> 3) & 1) << 3);

    load_stage(0, 0);
    load_stage(1, 1);
    for (int kc = 0; kc < 8; kc++) {
        if (kc < 7) {
            asm volatile("cp.async.wait_group 1;" ::: "memory");
        } else {
            asm volatile("cp.async.wait_group 0;" ::: "memory");
        }
        __syncthreads();
        if (kc + 2 < 8) load_stage(kc + 2, (kc + 2) % 3);
        uint32_t sb = smb + (kc % 3) * 65536;
        #pragma unroll
        for (int t = 0; t < 8; t++) {
            uint32_t Ab = sb + (t >> 2) * 16384;
            uint32_t Bb = sb + 32768 + (t >> 2) * 16384;
            const int kb = (t & 3) * 32 + selB * 16;
            uint32_t ah[2][4], bh[4][4];
            #pragma unroll
            for (int m = 0; m < 2; m++) {
                uint32_t ro = (mwo + m * 16 + aRow) * 128 + kb;
                ldsm4(ah[m], Ab + SWZ(ro));
            }
            #pragma unroll
            for (int ng = 0; ng < 4; ng++) {
                uint32_t ro = (nwo + ng * 16 + bRow) * 128 + kb;
                ldsm4(bh[ng], Bb + SWZ(ro));
            }
            #pragma unroll
            for (int m = 0; m < 2; m++)
                #pragma unroll
                for (int ng = 0; ng < 4; ng++) {
                    mma_f16(acc[m][2*ng],   ah[m], bh[ng][0], bh[ng][2]);
                    mma_f16(acc[m][2*ng+1], ah[m], bh[ng][1], bh[ng][3]);
                }
        }
    }
    __syncthreads();   // all reads done before epilogue staging overwrites

    // ---- epilogue: accums -> SMEM (scaled), residual + bias + fused BN stats ----
    float* red = (float*)sm;                       // 128 x 132 f32 = 67584 B < 196608
    const int r4 = l >> 2, c2 = (l & 3) * 2;
    #pragma unroll
    for (int m = 0; m < 2; m++)
        #pragma unroll
        for (int nt = 0; nt < 8; nt++) {
            int row = mwo + m * 16 + r4, col = nwo + nt * 8 + c2;
            *(float2*)&red[row * 132 + col] =
                make_float2(acc[m][nt][0] * LINV, acc[m][nt][1] * LINV);
            *(float2*)&red[(row + 8) * 132 + col] =
                make_float2(acc[m][nt][2] * LINV, acc[m][nt][3] * LINV);
        }
    __syncthreads();

    float* xbb = xb + ((size_t)b << 17) + (size_t)mt8 * 128 * DD;
    const int cc = tid & 127;
    const float bkv = bk[cc];
    float s = 0.f, q = 0.f;
    #pragma unroll 8
    for (int i = 0; i < 64; i++) {
        int idx = i * 256 + tid;
        int row = idx >> 7;
        float o = xbb[idx] + red[row * 132 + cc] + bkv;
        xbb[idx] = o;
        s += o; q += o * o;
    }
    __syncthreads();
    float* ss = red;                               // reuse staging
    float* qq = red + 256;
    ss[tid] = s; qq[tid] = q;
    __syncthreads();
    if (tid < 128) {
        s = ss[tid] + ss[tid + 128];
        q = qq[tid] + qq[tid + 128];
        atomicAdd(&g_stats[slot * 256 + tid], s);
        atomicAdd(&g_stats[slot * 256 + 128 + tid], q);
    }
}

// ---------------- pool (partial, atomics) + output ----------------
__global__ void pool_kernel(const float* __restrict__ xa, const float* __restrict__ xb,
                            const float* __restrict__ mask,
                            const float* __restrict__ g1, const float* __restrict__ be1,
                            const float* __restrict__ g2, const float* __restrict__ be2,
                            int slot1, int slot2) {
    int b = blockIdx.x, seg = blockIdx.y, t = threadIdx.x;
    int c = t & 127, half = t >> 7;
    __shared__ float s1[128], t1s[128], s2[128], t2s[128];
    if (t < 128) {
        float s = g_stats[slot1 * 256 + t], q = g_stats[slot1 * 256 + 128 + t];
        float mean = s * (1.f / CNT), var = q * (1.f / CNT) - mean * mean;
        float sc = g1[t] * rsqrtf(var + EPSV);
        s1[t] = sc; t1s[t] = be1[t] - mean * sc;
        s = g_stats[slot2 * 256 + t]; q = g_stats[slot2 * 256 + 128 + t];
        mean = s * (1.f / CNT); var = q * (1.f / CNT) - mean * mean;
        sc = g2[t] * rsqrtf(var + EPSV);
        s2[t] = sc; t2s[t] = be2[t] - mean * sc;
    }
    __syncthreads();
    float acc = 0.f, msum = 0.f;
    int r0 = seg * 128;
    for (int i = half; i < 128; i += 2) {
        int r = r0 + i;
        float m = mask[b * NN + r];
        float v = fmaf(s1[c], xa[(b * NN + r) * DD + c], t1s[c]) +
                  fmaf(s2[c], xb[(b * NN + r) * DD + c], t2s[c]);
        v = (v > 0.f) ? v : expm1f(v);
        acc += m * v;
        if (c == 0) msum += m;
    }
    __shared__ float red[256];
    red[t] = acc;
    __syncthreads();
    if (half == 0) atomicAdd(&g_pooled[b * DD + c], red[c] + red[c + 128]);
    __syncthreads();
    red[t] = (c == 0) ? msum : 0.f;
    __syncthreads();
    if (t == 0) atomicAdd(&g_den[b], red[0] + red[128]);
}

__global__ void out_kernel(const float* __restrict__ W2, const float* __restrict__ b2,
                           float* __restrict__ out) {
    int b = blockIdx.x, d = threadIdx.x;
    __shared__ float p[128];
    p[d] = g_pooled[b * DD + d];
    __syncthreads();
    float inv = 1.f / g_den[b];
    float accv = 0.f;
    #pragma unroll 4
    for (int c = 0; c < 128; c++) accv = fmaf(p[c], W2[c * 128 + d], accv);
    out[b * 128 + d] = accv * inv + b2[d];
}

// ---------------- host ----------------
extern "C" void kernel_launch(void* const* d_in, const int* in_sizes, int n_in,
                              void* d_out, int out_size) {
    const float* inputs = (const float*)d_in[0];
    const float* Lmat   = (const float*)d_in[1];
    const float* mask   = (const float*)d_in[2];
    const float* W1     = (const float*)d_in[3];
    const float* b1     = (const float*)d_in[4];
    const float* Wb     = (const float*)d_in[5];
    const float* bb     = (const float*)d_in[6];
    const float* gb     = (const float*)d_in[7];
    const float* beb    = (const float*)d_in[8];
    const float* g1     = (const float*)d_in[9];
    const float* be1    = (const float*)d_in[10];
    const float* g2     = (const float*)d_in[11];
    const float* be2    = (const float*)d_in[12];
    const float* W2     = (const float*)d_in[13];
    const float* b2     = (const float*)d_in[14];
    float* out = (float*)d_out;

    float *buf0, *buf1;
    cudaGetSymbolAddress((void**)&buf0, g_buf0);
    cudaGetSymbolAddress((void**)&buf1, g_buf1);

    cudaFuncSetAttribute(mma_gemm, cudaFuncAttributeMaxDynamicSharedMemorySize, MM_SMEM);
    cudaFuncSetAttribute(bnelu_mma, cudaFuncAttributeMaxDynamicSharedMemorySize, BM_SMEM);

    lconv_kernel<<<(BATCH * NN * NN) / 4 / 256, 256>>>(Lmat);
    wprep_all<<<NBLK, 256>>>(Wb);
    conv1_kernel<<<(BATCH * NN * 32) / 256, 256>>>(inputs, W1, b1);
    stats_kernel<<<256, 256>>>(buf0, 0);

    float* pa = buf0;   // x1
    float* pb = buf1;   // x2
    for (int k = 0; k < NBLK; k++) {
        dim3 grid(8, 16);
        bnelu_mma<<<grid, 256, BM_SMEM>>>(pa, k, gb + k * DD, beb + k * DD, k);
        mma_gemm<<<grid, 256, MM_SMEM>>>(pb, bb + k * DD, k + 1);
        float* tmp = pa; pa = pb; pb = tmp;
    }
    // pa = x1_final (stats slot 15), pb = x2_final (stats slot 14)
    dim3 pgrid(BATCH, 8);
    pool_kernel<<<pgrid, 256>>>(pa, pb, mask, g1, be1, g2, be2, NBLK, NBLK - 1);
    out_kernel<<<BATCH, 128>>>(W2, b2, out);
}

// round 13
// speedup vs baseline: 1.2153x; 1.1080x over previous
#include <cuda_runtime.h>
#include <cuda_bf16.h>
#include <cuda_fp16.h>
#include <math.h>
#include <stdint.h>

#define BATCH 16
#define NN 1024
#define DD 128
#define NBLK 15
#define CNT (BATCH*NN)
#define EPSV 1e-5f
#define LSCALE 256.0f
#define LINV (1.0f/256.0f)

// fast ELU: exp via MUFU ex2 path (~1e-7 rel err, fine vs fp16 pipeline noise)
__device__ __forceinline__ float elu_fast(float v) {
    return (v > 0.f) ? v : (__expf(v) - 1.f);
}

// ---------------- scratch (no allocation allowed) ----------------
__device__ float g_buf0[BATCH*NN*DD];                 // 8 MB (x ping)
__device__ float g_buf1[BATCH*NN*DD];                 // 8 MB (x pong)
__device__ __half g_lhf[(size_t)BATCH*NN*NN];         // 32 MB  fp16(256*L)
__device__ __half g_whf[BATCH*DD*NN];                 // 4 MB  (h*Wk)^T fp16 [b][e][n]
__device__ __half g_wthf[NBLK*DD*DD];                 // W^T hi fp16 [k][e][d]
__device__ __half g_wtlf[NBLK*DD*DD];                 // W^T lo fp16
__device__ float g_stats[17*2*DD];                    // [slot][sum|sumsq][128]
__device__ float g_pooled[BATCH*DD];
__device__ float g_den[BATCH];

// ---------------- helpers ----------------
__device__ __forceinline__ uint32_t smem_u32(const void* p) {
    uint32_t a;
    asm("{ .reg .u64 t; cvta.to.shared.u64 t, %1; cvt.u32.u64 %0, t; }"
        : "=r"(a) : "l"(p));
    return a;
}
#define SWZ(o) ((o) ^ (((o) >> 3) & 0x70))

__device__ __forceinline__ void ldsm4(uint32_t* r, uint32_t a) {
    asm volatile("ldmatrix.sync.aligned.m8n8.x4.shared.b16 {%0,%1,%2,%3}, [%4];"
        : "=r"(r[0]), "=r"(r[1]), "=r"(r[2]), "=r"(r[3]) : "r"(a));
}
__device__ __forceinline__ void mma_f16(float* c, const uint32_t* a,
                                        uint32_t b0, uint32_t b1) {
    asm volatile("mma.sync.aligned.m16n8k16.row.col.f32.f16.f16.f32 "
        "{%0,%1,%2,%3}, {%4,%5,%6,%7}, {%8,%9}, {%0,%1,%2,%3};"
        : "+f"(c[0]), "+f"(c[1]), "+f"(c[2]), "+f"(c[3])
        : "r"(a[0]), "r"(a[1]), "r"(a[2]), "r"(a[3]), "r"(b0), "r"(b1));
}

// ---------------- small kernels ----------------
// lconv also zeroes the stats/pool scratch (block 0) — saves a launch.
__global__ void lconv_kernel(const float* __restrict__ L) {
    if (blockIdx.x == 0) {
        for (int i = threadIdx.x; i < 17*2*DD; i += 256) g_stats[i] = 0.f;
        for (int i = threadIdx.x; i < BATCH*DD; i += 256) g_pooled[i] = 0.f;
        if (threadIdx.x < BATCH) g_den[threadIdx.x] = 0.f;
    }
    int g = blockIdx.x * 256 + threadIdx.x;
    float4 v = ((const float4*)L)[g];
    union { __half h[4]; uint2 u; } p;
    p.h[0] = __float2half(v.x * LSCALE);
    p.h[1] = __float2half(v.y * LSCALE);
    p.h[2] = __float2half(v.z * LSCALE);
    p.h[3] = __float2half(v.w * LSCALE);
    ((uint2*)g_lhf)[g] = p.u;
}

__global__ void wprep_all(const float* __restrict__ Wb) {
    int k = blockIdx.x;
    const float* W = Wb + k * DD * DD;
    __half* oh = g_wthf + k * DD * DD;
    __half* ol = g_wtlf + k * DD * DD;
    for (int i = threadIdx.x; i < DD * DD; i += blockDim.x) {
        int e = i >> 7, d = i & 127;
        float v = W[d * DD + e];
        __half hi = __float2half(v);
        oh[i] = hi;
        ol[i] = __float2half(v - __half2float(hi));
    }
}

__global__ void conv1_kernel(const float* __restrict__ inp,
                             const float* __restrict__ W1,
                             const float* __restrict__ b1) {
    int gid = blockIdx.x * blockDim.x + threadIdx.x;   // over B*N*32 float4s
    int row = gid >> 5, c4 = gid & 31;
    const float* x = inp + row * 3;
    float x0 = x[0], x1 = x[1], x2 = x[2];
    float4 w0 = *(const float4*)&W1[c4 * 4];
    float4 w1 = *(const float4*)&W1[128 + c4 * 4];
    float4 w2 = *(const float4*)&W1[256 + c4 * 4];
    float4 bv = *(const float4*)&b1[c4 * 4];
    float4 o;
    o.x = fmaf(x0, w0.x, fmaf(x1, w1.x, fmaf(x2, w2.x, bv.x)));
    o.y = fmaf(x0, w0.y, fmaf(x1, w1.y, fmaf(x2, w2.y, bv.y)));
    o.z = fmaf(x0, w0.z, fmaf(x1, w1.z, fmaf(x2, w2.z, bv.z)));
    o.w = fmaf(x0, w0.w, fmaf(x1, w1.w, fmaf(x2, w2.w, bv.w)));
    ((float4*)g_buf0)[gid] = o;
    ((float4*)g_buf1)[gid] = make_float4(0.f, 0.f, 0.f, 0.f);
}

// vectorized: 256 blocks x 64 rows; thread = (c4, rsub) with 8 float4 loads (MLP 8)
__global__ void stats_kernel(const float* __restrict__ x, int slot) {
    int c4 = threadIdx.x & 31;        // float4 column
    int rsub = threadIdx.x >> 5;      // 0..7
    int row0 = blockIdx.x * 64;
    float4 s4 = make_float4(0.f,0.f,0.f,0.f), q4 = make_float4(0.f,0.f,0.f,0.f);
    for (int i = rsub; i < 64; i += 8) {
        float4 v = ((const float4*)x)[(size_t)(row0 + i) * 32 + c4];
        s4.x += v.x; s4.y += v.y; s4.z += v.z; s4.w += v.w;
        q4.x += v.x*v.x; q4.y += v.y*v.y; q4.z += v.z*v.z; q4.w += v.w*v.w;
    }
    __shared__ float4 ss[256], qq[256];
    ss[threadIdx.x] = s4; qq[threadIdx.x] = q4;
    __syncthreads();
    if (rsub == 0) {
        #pragma unroll
        for (int j = 1; j < 8; j++) {
            float4 a = ss[j * 32 + c4], b = qq[j * 32 + c4];
            s4.x += a.x; s4.y += a.y; s4.z += a.z; s4.w += a.w;
            q4.x += b.x; q4.y += b.y; q4.z += b.z; q4.w += b.w;
        }
        int c = c4 * 4;
        atomicAdd(&g_stats[slot * 256 + c + 0], s4.x);
        atomicAdd(&g_stats[slot * 256 + c + 1], s4.y);
        atomicAdd(&g_stats[slot * 256 + c + 2], s4.z);
        atomicAdd(&g_stats[slot * 256 + c + 3], s4.w);
        atomicAdd(&g_stats[slot * 256 + 128 + c + 0], q4.x);
        atomicAdd(&g_stats[slot * 256 + 128 + c + 1], q4.y);
        atomicAdd(&g_stats[slot * 256 + 128 + c + 2], q4.z);
        atomicAdd(&g_stats[slot * 256 + 128 + c + 3], q4.w);
    }
}

// ---------------- bnelu + (h*Wk)^T via fp16 tensor cores (2-pass, W hi/lo) ----------------
// SMEM: W_hi 2x16K at 0, W_lo 2x16K at 32K, h 2x16K at 64K  => 96 KB
#define BM_SMEM 98304
__global__ void __launch_bounds__(256)
bnelu_mma(const float* __restrict__ x, int blk,
          const float* __restrict__ gam, const float* __restrict__ bet, int slot) {
    extern __shared__ __align__(1024) char sm[];
    const uint32_t smb = smem_u32(sm);
    __shared__ float sc[128], tsh[128];
    const int tid = threadIdx.x, w = tid >> 5, l = tid & 31;
    const int b = blockIdx.y, nt = blockIdx.x;

    if (tid < 128) {
        float s = g_stats[slot * 256 + tid], q = g_stats[slot * 256 + 128 + tid];
        float mean = s * (1.f / CNT), var = q * (1.f / CNT) - mean * mean;
        float k = gam[tid] * rsqrtf(var + EPSV);
        sc[tid] = k; tsh[tid] = bet[tid] - mean * k;
    }

    const __half* wth = g_wthf + blk * DD * DD;
    const __half* wtl = g_wtlf + blk * DD * DD;
    #pragma unroll
    for (int i = 0; i < 8; i++) {
        int c = i * 256 + tid;                    // 16B chunk over 2048
        int e = c >> 4, ch = c & 15;
        uint32_t off = (uint32_t)(ch >> 3) * 16384 + SWZ(e * 128 + (ch & 7) * 16);
        *(float4*)(sm + off) = *(const float4*)(wth + e * 128 + ch * 8);
        *(float4*)(sm + 32768 + off) = *(const float4*)(wtl + e * 128 + ch * 8);
    }
    __syncthreads();

    const float* xb = x + ((size_t)b << 17) + (size_t)nt * 128 * DD;
    #pragma unroll 8
    for (int i = 0; i < 64; i++) {
        int idx = i * 256 + tid;
        int n = idx >> 7, d = idx & 127;
        float v = elu_fast(fmaf(sc[d], xb[idx], tsh[d]));
        uint32_t o = (uint32_t)(d >> 6) * 16384 + SWZ(n * 128 + (d & 63) * 2);
        *(__half*)(sm + 65536 + o) = __float2half(v);
    }
    __syncthreads();

    float acc[2][8][4] = {};
    const int mwo = (w & 3) * 32, nwo = (w >> 2) * 64;
    const int aRow = l & 15, selB = l >> 4;
    const int bRow = (l & 7) + (((l >> 3) & 1) << 3);

    #pragma unroll
    for (int ks = 0; ks < 2; ks++) {
        uint32_t Ah = smb + ks * 16384;
        uint32_t Al = smb + 32768 + ks * 16384;
        uint32_t Bh = smb + 65536 + ks * 16384;
        #pragma unroll
        for (int t = 0; t < 4; t++) {
            const int kb = t * 32 + selB * 16;
            uint32_t ah[2][4], al[2][4], bh[4][4];
            #pragma unroll
            for (int m = 0; m < 2; m++) {
                uint32_t ro = (mwo + m * 16 + aRow) * 128 + kb;
                ldsm4(ah[m], Ah + SWZ(ro));
                ldsm4(al[m], Al + SWZ(ro));
            }
            #pragma unroll
            for (int ng = 0; ng < 4; ng++) {
                uint32_t ro = (nwo + ng * 16 + bRow) * 128 + kb;
                ldsm4(bh[ng], Bh + SWZ(ro));
            }
            // pass 1: W_hi * h
            #pragma unroll
            for (int m = 0; m < 2; m++)
                #pragma unroll
                for (int ng = 0; ng < 4; ng++) {
                    mma_f16(acc[m][2*ng],   ah[m], bh[ng][0], bh[ng][2]);
                    mma_f16(acc[m][2*ng+1], ah[m], bh[ng][1], bh[ng][3]);
                }
            // pass 2: W_lo * h
            #pragma unroll
            for (int m = 0; m < 2; m++)
                #pragma unroll
                for (int ng = 0; ng < 4; ng++) {
                    mma_f16(acc[m][2*ng],   al[m], bh[ng][0], bh[ng][2]);
                    mma_f16(acc[m][2*ng+1], al[m], bh[ng][1], bh[ng][3]);
                }
        }
    }
    __syncthreads();

    float* red = (float*)sm;                   // 128 x 132  (rows = e, cols = n)
    const int r4 = l >> 2, c2 = (l & 3) * 2;
    #pragma unroll
    for (int m = 0; m < 2; m++)
        #pragma unroll
        for (int ntile = 0; ntile < 8; ntile++) {
            int row = mwo + m * 16 + r4, col = nwo + ntile * 8 + c2;
            *(float2*)&red[row * 132 + col] = make_float2(acc[m][ntile][0], acc[m][ntile][1]);
            *(float2*)&red[(row + 8) * 132 + col] = make_float2(acc[m][ntile][2], acc[m][ntile][3]);
        }
    __syncthreads();

    const size_t obase = (size_t)b * (DD * NN) + (size_t)nt * 128;
    #pragma unroll 8
    for (int i = 0; i < 64; i++) {
        int idx = i * 256 + tid;
        int e = idx >> 7, n = idx & 127;
        g_whf[obase + (size_t)e * NN + n] = __float2half(red[e * 132 + n]);
    }
}

// ---------------- fp16 warp-MMA big GEMM (1-pass, BK=128, 3-stage) ----------------
// grid (8, 16), 256 threads (8 warps, 32x64 warp tiles).
// Stage = A[128x128] 32K (two 16K k-blocks) + B same = 64 KB; 3 stages = 192 KB.
#define MM_SMEM 196608
__global__ void __launch_bounds__(256)
mma_gemm(float* __restrict__ xb, const float* __restrict__ bk, int slot) {
    extern __shared__ __align__(1024) char sm[];
    const uint32_t smb = smem_u32(sm);
    const int tid = threadIdx.x, w = tid >> 5, l = tid & 31;
    const int b = blockIdx.y, mt8 = blockIdx.x;

    const size_t aoff = (size_t)b * NN * NN + (size_t)mt8 * 128 * NN;
    const size_t boff = (size_t)b * (DD * NN);
    const __half* srcp[2] = { g_lhf + aoff, g_whf + boff };

    // stage layout: mat(A/B) * 32768 + kblk * 16384 + SWZ(row*128 + q*16)
    auto load_stage = [&](int kc, int st) {
        uint32_t dst0 = smb + st * 65536;
        #pragma unroll
        for (int i = 0; i < 16; i++) {
            int c = i * 256 + tid;                 // 0..4095 16B chunks
            int mat = c >> 11, rem = c & 2047;
            int r = rem >> 4, ch = rem & 15;
            int kblk = ch >> 3, q = ch & 7;
            const __half* s = srcp[mat] + (size_t)r * NN + kc * 128 + kblk * 64 + q * 8;
            uint32_t d = dst0 + mat * 32768 + kblk * 16384 + SWZ(r * 128 + q * 16);
            asm volatile("cp.async.cg.shared.global [%0], [%1], 16;" :: "r"(d), "l"(s));
        }
        asm volatile("cp.async.commit_group;" ::: "memory");
    };

    float acc[2][8][4] = {};
    const int mwo = (w & 3) * 32, nwo = (w >> 2) * 64;
    const int aRow = l & 15, selB = l >> 4;
    const int bRow = (l & 7) + (((l >> 3) & 1) << 3);

    load_stage(0, 0);
    load_stage(1, 1);
    for (int kc = 0; kc < 8; kc++) {
        if (kc < 7) {
            asm volatile("cp.async.wait_group 1;" ::: "memory");
        } else {
            asm volatile("cp.async.wait_group 0;" ::: "memory");
        }
        __syncthreads();
        if (kc + 2 < 8) load_stage(kc + 2, (kc + 2) % 3);
        uint32_t sb = smb + (kc % 3) * 65536;
        #pragma unroll
        for (int t = 0; t < 8; t++) {
            uint32_t Ab = sb + (t >> 2) * 16384;
            uint32_t Bb = sb + 32768 + (t >> 2) * 16384;
            const int kb = (t & 3) * 32 + selB * 16;
            uint32_t ah[2][4], bh[4][4];
            #pragma unroll
            for (int m = 0; m < 2; m++) {
                uint32_t ro = (mwo + m * 16 + aRow) * 128 + kb;
                ldsm4(ah[m], Ab + SWZ(ro));
            }
            #pragma unroll
            for (int ng = 0; ng < 4; ng++) {
                uint32_t ro = (nwo + ng * 16 + bRow) * 128 + kb;
                ldsm4(bh[ng], Bb + SWZ(ro));
            }
            #pragma unroll
            for (int m = 0; m < 2; m++)
                #pragma unroll
                for (int ng = 0; ng < 4; ng++) {
                    mma_f16(acc[m][2*ng],   ah[m], bh[ng][0], bh[ng][2]);
                    mma_f16(acc[m][2*ng+1], ah[m], bh[ng][1], bh[ng][3]);
                }
        }
    }
    __syncthreads();   // all reads done before epilogue staging overwrites

    // ---- epilogue: accums -> SMEM (scaled), residual + bias + fused BN stats ----
    float* red = (float*)sm;                       // 128 x 132 f32 = 67584 B < 196608
    const int r4 = l >> 2, c2 = (l & 3) * 2;
    #pragma unroll
    for (int m = 0; m < 2; m++)
        #pragma unroll
        for (int nt = 0; nt < 8; nt++) {
            int row = mwo + m * 16 + r4, col = nwo + nt * 8 + c2;
            *(float2*)&red[row * 132 + col] =
                make_float2(acc[m][nt][0] * LINV, acc[m][nt][1] * LINV);
            *(float2*)&red[(row + 8) * 132 + col] =
                make_float2(acc[m][nt][2] * LINV, acc[m][nt][3] * LINV);
        }
    __syncthreads();

    float* xbb = xb + ((size_t)b << 17) + (size_t)mt8 * 128 * DD;
    const int cc = tid & 127;
    const float bkv = bk[cc];
    float s = 0.f, q = 0.f;
    #pragma unroll 8
    for (int i = 0; i < 64; i++) {
        int idx = i * 256 + tid;
        int row = idx >> 7;
        float o = xbb[idx] + red[row * 132 + cc] + bkv;
        xbb[idx] = o;
        s += o; q += o * o;
    }
    __syncthreads();
    float* ss = red;                               // reuse staging
    float* qq = red + 256;
    ss[tid] = s; qq[tid] = q;
    __syncthreads();
    if (tid < 128) {
        s = ss[tid] + ss[tid + 128];
        q = qq[tid] + qq[tid + 128];
        atomicAdd(&g_stats[slot * 256 + tid], s);
        atomicAdd(&g_stats[slot * 256 + 128 + tid], q);
    }
}

// ---------------- pool (partial, atomics) + output ----------------
__global__ void pool_kernel(const float* __restrict__ xa, const float* __restrict__ xb,
                            const float* __restrict__ mask,
                            const float* __restrict__ g1, const float* __restrict__ be1,
                            const float* __restrict__ g2, const float* __restrict__ be2,
                            int slot1, int slot2) {
    int b = blockIdx.x, seg = blockIdx.y, t = threadIdx.x;
    int c = t & 127, half = t >> 7;
    __shared__ float s1[128], t1s[128], s2[128], t2s[128];
    if (t < 128) {
        float s = g_stats[slot1 * 256 + t], q = g_stats[slot1 * 256 + 128 + t];
        float mean = s * (1.f / CNT), var = q * (1.f / CNT) - mean * mean;
        float sc = g1[t] * rsqrtf(var + EPSV);
        s1[t] = sc; t1s[t] = be1[t] - mean * sc;
        s = g_stats[slot2 * 256 + t]; q = g_stats[slot2 * 256 + 128 + t];
        mean = s * (1.f / CNT); var = q * (1.f / CNT) - mean * mean;
        sc = g2[t] * rsqrtf(var + EPSV);
        s2[t] = sc; t2s[t] = be2[t] - mean * sc;
    }
    __syncthreads();
    float acc = 0.f, msum = 0.f;
    int r0 = seg * 128;
    for (int i = half; i < 128; i += 2) {
        int r = r0 + i;
        float m = mask[b * NN + r];
        float v = fmaf(s1[c], xa[(b * NN + r) * DD + c], t1s[c]) +
                  fmaf(s2[c], xb[(b * NN + r) * DD + c], t2s[c]);
        v = elu_fast(v);
        acc += m * v;
        if (c == 0) msum += m;
    }
    __shared__ float red[256];
    red[t] = acc;
    __syncthreads();
    if (half == 0) atomicAdd(&g_pooled[b * DD + c], red[c] + red[c + 128]);
    __syncthreads();
    red[t] = (c == 0) ? msum : 0.f;
    __syncthreads();
    if (t == 0) atomicAdd(&g_den[b], red[0] + red[128]);
}

__global__ void out_kernel(const float* __restrict__ W2, const float* __restrict__ b2,
                           float* __restrict__ out) {
    int b = blockIdx.x, d = threadIdx.x;
    __shared__ float p[128];
    p[d] = g_pooled[b * DD + d];
    __syncthreads();
    float inv = 1.f / g_den[b];
    float accv = 0.f;
    #pragma unroll 4
    for (int c = 0; c < 128; c++) accv = fmaf(p[c], W2[c * 128 + d], accv);
    out[b * 128 + d] = accv * inv + b2[d];
}

// ---------------- host ----------------
extern "C" void kernel_launch(void* const* d_in, const int* in_sizes, int n_in,
                              void* d_out, int out_size) {
    const float* inputs = (const float*)d_in[0];
    const float* Lmat   = (const float*)d_in[1];
    const float* mask   = (const float*)d_in[2];
    const float* W1     = (const float*)d_in[3];
    const float* b1     = (const float*)d_in[4];
    const float* Wb     = (const float*)d_in[5];
    const float* bb     = (const float*)d_in[6];
    const float* gb     = (const float*)d_in[7];
    const float* beb    = (const float*)d_in[8];
    const float* g1     = (const float*)d_in[9];
    const float* be1    = (const float*)d_in[10];
    const float* g2     = (const float*)d_in[11];
    const float* be2    = (const float*)d_in[12];
    const float* W2     = (const float*)d_in[13];
    const float* b2     = (const float*)d_in[14];
    float* out = (float*)d_out;

    float *buf0, *buf1;
    cudaGetSymbolAddress((void**)&buf0, g_buf0);
    cudaGetSymbolAddress((void**)&buf1, g_buf1);

    cudaFuncSetAttribute(mma_gemm, cudaFuncAttributeMaxDynamicSharedMemorySize, MM_SMEM);
    cudaFuncSetAttribute(bnelu_mma, cudaFuncAttributeMaxDynamicSharedMemorySize, BM_SMEM);

    lconv_kernel<<<(BATCH * NN * NN) / 4 / 256, 256>>>(Lmat);
    wprep_all<<<NBLK, 256>>>(Wb);
    conv1_kernel<<<(BATCH * NN * 32) / 256, 256>>>(inputs, W1, b1);
    stats_kernel<<<256, 256>>>(buf0, 0);

    float* pa = buf0;   // x1
    float* pb = buf1;   // x2
    for (int k = 0; k < NBLK; k++) {
        dim3 grid(8, 16);
        bnelu_mma<<<grid, 256, BM_SMEM>>>(pa, k, gb + k * DD, beb + k * DD, k);
        mma_gemm<<<grid, 256, MM_SMEM>>>(pb, bb + k * DD, k + 1);
        float* tmp = pa; pa = pb; pb = tmp;
    }
    // pa = x1_final (stats slot 15), pb = x2_final (stats slot 14)
    dim3 pgrid(BATCH, 8);
    pool_kernel<<<pgrid, 256>>>(pa, pb, mask, g1, be1, g2, be2, NBLK, NBLK - 1);
    out_kernel<<<BATCH, 128>>>(W2, b2, out);
}